// round 14
// baseline (speedup 1.0000x reference)
#include <cuda_runtime.h>
#include <cuda_fp16.h>
#include <cstdint>

#define NH   16
#define DM   1024
#define HDIM 64
#define NB   4
#define SEQ  2048
#define MTOT (NB * SEQ)   // 8192

__device__ __half g_Q[NB * NH * SEQ * HDIM];
__device__ __half g_K[NB * NH * SEQ * HDIM];
__device__ __half g_V[NB * NH * SEQ * HDIM];
__device__ __half g_Xh[(size_t)MTOT * DM];
__device__ __half g_Wh[3][(size_t)DM * DM];

#define LOG2E 1.44269504088896f

__device__ __forceinline__ uint32_t smem_u32(const void* p) {
    uint32_t a;
    asm("{ .reg .u64 t; cvta.to.shared.u64 t, %1; cvt.u32.u64 %0, t; }" : "=r"(a) : "l"(p));
    return a;
}
__device__ __forceinline__ void mma_f16(float* c, const uint32_t* a, const uint32_t* b) {
    asm volatile(
        "mma.sync.aligned.m16n8k16.row.col.f32.f16.f16.f32 "
        "{%0,%1,%2,%3},{%4,%5,%6,%7},{%8,%9},{%0,%1,%2,%3};"
        : "+f"(c[0]), "+f"(c[1]), "+f"(c[2]), "+f"(c[3])
        : "r"(a[0]), "r"(a[1]), "r"(a[2]), "r"(a[3]), "r"(b[0]), "r"(b[1]));
}
#define LDMX4(r0,r1,r2,r3,addr) \
    asm volatile("ldmatrix.sync.aligned.m8n8.x4.shared.b16 {%0,%1,%2,%3}, [%4];" \
        : "=r"(r0),"=r"(r1),"=r"(r2),"=r"(r3) : "r"(addr))
#define LDMX4T(r0,r1,r2,r3,addr) \
    asm volatile("ldmatrix.sync.aligned.m8n8.x4.trans.shared.b16 {%0,%1,%2,%3}, [%4];" \
        : "=r"(r0),"=r"(r1),"=r"(r2),"=r"(r3) : "r"(addr))
#define CP16(dst, src) \
    asm volatile("cp.async.cg.shared.global [%0], [%1], 16;" :: "r"(dst), "l"(src))
#define CPCOMMIT() asm volatile("cp.async.commit_group;" ::: "memory")
#define CPWAIT0()  asm volatile("cp.async.wait_group 0;" ::: "memory")
#define CPWAIT1()  asm volatile("cp.async.wait_group 1;" ::: "memory")

__device__ __forceinline__ uint32_t packh2(float x, float y) {
    __half2 h = __floats2half2_rn(x, y);
    return *(uint32_t*)&h;
}
__device__ __forceinline__ uint32_t ex2h2(uint32_t x) {
    uint32_t y;
    asm("ex2.approx.f16x2 %0, %1;" : "=r"(y) : "r"(x));
    return y;
}
__device__ __forceinline__ uint32_t hadd2u(uint32_t a, uint32_t b) {
    uint32_t y;
    asm("add.f16x2 %0, %1, %2;" : "=r"(y) : "r"(a), "r"(b));
    return y;
}
__device__ __forceinline__ uint32_t swz(uint32_t o) { return o ^ ((o >> 3) & 0x70); }

// ======================= fp32 -> fp16 conversion (16 elems/thread) =====
__global__ __launch_bounds__(256) void f2h_kernel(
    const float* __restrict__ X, const float* __restrict__ Wq,
    const float* __restrict__ Wk, const float* __restrict__ Wv)
{
    int y = blockIdx.y;
    const float* src; __half* dst; size_t n;
    if (y == 0)      { src = X;  dst = g_Xh;    n = (size_t)MTOT * DM; }
    else if (y == 1) { src = Wq; dst = g_Wh[0]; n = (size_t)DM * DM; }
    else if (y == 2) { src = Wk; dst = g_Wh[1]; n = (size_t)DM * DM; }
    else             { src = Wv; dst = g_Wh[2]; n = (size_t)DM * DM; }
    size_t i = ((size_t)blockIdx.x * 256 + threadIdx.x) * 16;
    if (i >= n) return;
    float4 a = *(const float4*)(src + i);
    float4 b = *(const float4*)(src + i + 4);
    float4 c = *(const float4*)(src + i + 8);
    float4 d = *(const float4*)(src + i + 12);
    uint4 u0, u1;
    u0.x = packh2(a.x, a.y); u0.y = packh2(a.z, a.w);
    u0.z = packh2(b.x, b.y); u0.w = packh2(b.z, b.w);
    u1.x = packh2(c.x, c.y); u1.y = packh2(c.z, c.w);
    u1.z = packh2(d.x, d.y); u1.w = packh2(d.z, d.w);
    *(uint4*)(dst + i)     = u0;
    *(uint4*)(dst + i + 8) = u1;
}

// ======================= QKV GEMM: 3-stage cp.async (frozen R11) =======
#define ROWA 40
#define ROWB 136
#define ABUF (128 * ROWA * 2)
#define BBUF (32 * ROWB * 2)
#define QKV_SMEM (3 * (ABUF + BBUF))
#define KITERS (DM / 32)

__global__ __launch_bounds__(256) void qkv_kernel(
    const float* __restrict__ bq, const float* __restrict__ bk,
    const float* __restrict__ bv)
{
    extern __shared__ __half qsm[];
    __half* Ash = qsm;
    __half* Bsh = qsm + 3 * 128 * ROWA;

    const int z = blockIdx.z;
    const __half* Xh = g_Xh;
    const __half* W  = g_Wh[z];
    const float* bias = (z == 0) ? bq : (z == 1) ? bk : bv;
    __half* out = (z == 0) ? g_Q : (z == 1) ? g_K : g_V;
    const float osc = (z == 0) ? (0.125f * LOG2E) : 1.0f;

    const int t = threadIdx.x, lane = t & 31, wid = t >> 5;
    const int wm = (wid >> 2) * 64, wn = (wid & 3) * 32;
    const int g = lane >> 2, q = lane & 3;
    const int n0 = blockIdx.x * 128, m0 = blockIdx.y * 128;

    float c[4][4][4] = {};

    const __half* aptr = Xh + (size_t)(m0 + (t >> 1)) * DM + (t & 1) * 16;
    const __half* bptr = W + (size_t)(t >> 3) * DM + n0 + (t & 7) * 16;
    const uint32_t ast = smem_u32(Ash) + (uint32_t)(t >> 1) * (ROWA * 2) + (t & 1) * 32;
    const uint32_t bst = smem_u32(Bsh) + (uint32_t)(t >> 3) * (ROWB * 2) + (t & 7) * 32;

    const uint32_t Ab = smem_u32(Ash), Bb = smem_u32(Bsh);
    const uint32_t a_ad0 = Ab + (uint32_t)(wm + (lane & 15)) * (ROWA * 2) + ((lane & 16) ? 16 : 0);
    const uint32_t b_ad0 = Bb + (uint32_t)((lane & 7) + ((lane & 8) ? 8 : 0)) * (ROWB * 2)
                              + (uint32_t)(wn + ((lane & 16) ? 8 : 0)) * 2;

    #pragma unroll
    for (int pg = 0; pg < 2; pg++) {
        const char* asrc = (const char*)(aptr + pg * 32);
        const char* bsrc = (const char*)(bptr + (size_t)(pg * 32) * DM);
        CP16(ast + pg * ABUF, asrc);      CP16(ast + pg * ABUF + 16, asrc + 16);
        CP16(bst + pg * BBUF, bsrc);      CP16(bst + pg * BBUF + 16, bsrc + 16);
        CPCOMMIT();
    }
    CPWAIT1();
    __syncthreads();

    for (int it = 0; it < KITERS; it++) {
        const int cur = it % 3;
        if (it + 2 < KITERS) {
            const int sl = (it + 2) % 3;
            const char* asrc = (const char*)(aptr + (it + 2) * 32);
            const char* bsrc = (const char*)(bptr + (size_t)(it + 2) * 32 * DM);
            CP16(ast + sl * ABUF, asrc);      CP16(ast + sl * ABUF + 16, asrc + 16);
            CP16(bst + sl * BBUF, bsrc);      CP16(bst + sl * BBUF + 16, bsrc + 16);
            CPCOMMIT();
        }

        const uint32_t a_ad = a_ad0 + cur * ABUF;
        const uint32_t b_ad = b_ad0 + cur * BBUF;
        #pragma unroll
        for (int kc = 0; kc < 2; kc++) {
            uint32_t af[4][4];
            #pragma unroll
            for (int mt = 0; mt < 4; mt++)
                LDMX4(af[mt][0], af[mt][1], af[mt][2], af[mt][3],
                      a_ad + (uint32_t)mt * 16 * (ROWA * 2) + kc * 32);
            uint32_t bf[4][2];
            #pragma unroll
            for (int p = 0; p < 2; p++) {
                uint32_t r0, r1, r2, r3;
                LDMX4T(r0, r1, r2, r3,
                       b_ad + (uint32_t)kc * 16 * (ROWB * 2) + p * 32);
                bf[2 * p][0] = r0; bf[2 * p][1] = r1;
                bf[2 * p + 1][0] = r2; bf[2 * p + 1][1] = r3;
            }
            #pragma unroll
            for (int mt = 0; mt < 4; mt++)
                #pragma unroll
                for (int nt = 0; nt < 4; nt++)
                    mma_f16(c[mt][nt], af[mt], bf[nt]);
        }

        if (it + 2 < KITERS) CPWAIT1(); else CPWAIT0();
        __syncthreads();
    }

    #pragma unroll
    for (int nt = 0; nt < 4; nt++) {
        int n = n0 + wn + nt * 8 + 2 * q;
        int h = n >> 6, hd = n & 63;
        float bx = bias[n], by = bias[n + 1];
        #pragma unroll
        for (int mt = 0; mt < 4; mt++) {
            int m = m0 + wm + mt * 16 + g;
            int b0i = m >> 11, s0i = m & 2047;
            int b1i = (m + 8) >> 11, s1i = (m + 8) & 2047;
            __half2 r0 = __floats2half2_rn((c[mt][nt][0] + bx) * osc, (c[mt][nt][1] + by) * osc);
            __half2 r1 = __floats2half2_rn((c[mt][nt][2] + bx) * osc, (c[mt][nt][3] + by) * osc);
            *(__half2*)&out[((size_t)(b0i * NH + h) * SEQ + s0i) * HDIM + hd] = r0;
            *(__half2*)&out[((size_t)(b1i * NH + h) * SEQ + s1i) * HDIM + hd] = r1;
        }
    }
}

// ======================= Flash attention: hadd2 lsum, hoisted mask =====
#define SQ_Q    0
#define SQ_KV   16384                  // 4 stages x (K 8KB + V 8KB)
#define SQ_MSK  (16384 + 4 * 16384)    // 81920; [NT][32] u32 = 4 KB
#define SQ_TOT  (81920 + 4096)
#define NT      (SEQ / 64)

__global__ __launch_bounds__(256, 2) void attn_kernel(
    const float* __restrict__ mask,  // [B,S]
    float* __restrict__ out)         // [B,S,D]
{
    extern __shared__ char sm[];
    const uint32_t sb = smem_u32(sm);
    const int t = threadIdx.x, lane = t & 31, wid = t >> 5;
    const int g = lane >> 2, q = lane & 3;
    const int wq = wid * 16;

    const int bh = blockIdx.y;
    const int b = bh >> 4, h = bh & 15;
    const int q0 = blockIdx.x * 128;

    const __half* Qg = g_Q + (size_t)bh * SEQ * HDIM + (size_t)q0 * HDIM;
    const __half* Kg = g_K + (size_t)bh * SEQ * HDIM;
    const __half* Vg = g_V + (size_t)bh * SEQ * HDIM;
    const float* mk = mask + (size_t)b * SEQ;
    uint32_t* mskh = (uint32_t*)(sm + SQ_MSK);   // [NT][32] half2, *LOG2E

    const int kr = t >> 3, kj = t & 7;
    const uint32_t koffA = swz((uint32_t)kr * 128 + kj * 16);
    const uint32_t koffB = swz((uint32_t)(kr + 32) * 128 + kj * 16);

    auto stage_tile = [&](int tile, const int st) {
        const uint32_t kb = sb + SQ_KV + (uint32_t)st * 16384;
        const char* ksA = (const char*)(Kg + ((size_t)tile * 64 + kr) * HDIM) + kj * 16;
        const char* ksB = (const char*)(Kg + ((size_t)tile * 64 + kr + 32) * HDIM) + kj * 16;
        const char* vsA = (const char*)(Vg + ((size_t)tile * 64 + kr) * HDIM) + kj * 16;
        const char* vsB = (const char*)(Vg + ((size_t)tile * 64 + kr + 32) * HDIM) + kj * 16;
        CP16(kb + koffA, ksA);
        CP16(kb + koffB, ksB);
        CP16(kb + 8192 + koffA, vsA);
        CP16(kb + 8192 + koffB, vsB);
    };

    stage_tile(0, 0);
    stage_tile(1, 1);
    CPCOMMIT();
    {   // stage Q
        int r = t >> 1;
        const uint4* src = (const uint4*)(Qg + (size_t)r * HDIM) + (t & 1) * 4;
        #pragma unroll
        for (int j = 0; j < 4; j++)
            *(uint4*)(sm + SQ_Q + swz((uint32_t)r * 128 + ((t & 1) * 4 + j) * 16)) = src[j];
    }
    {   // pre-stage whole mask row: NT*32 = 1024 half2 entries, 4 per thread
        #pragma unroll
        for (int j = 0; j < 4; j++) {
            int e = t + j * 256;
            mskh[e] = packh2(mk[2 * e] * LOG2E, mk[2 * e + 1] * LOG2E);
        }
    }
    CPWAIT0();
    __syncthreads();

    uint32_t qa[4][4];
    #pragma unroll
    for (int kc = 0; kc < 4; kc++) {
        uint32_t ad = sb + SQ_Q + swz((uint32_t)(wq + (lane & 15)) * 128
                                      + kc * 32 + ((lane & 16) ? 16 : 0));
        LDMX4(qa[kc][0], qa[kc][1], qa[kc][2], qa[kc][3], ad);
    }

    float o[8][4] = {};
    float lsum0 = 0.0f, lsum1 = 0.0f;   // rows g, g+8 partial sums (this thread's cols)

    auto compute_tile = [&](const int st, const int tile) {
        const uint32_t kb = sb + SQ_KV + (uint32_t)st * 16384;
        float s[8][4] = {};
        #pragma unroll
        for (int kc = 0; kc < 4; kc++) {
            uint32_t bf[8][2];
            #pragma unroll
            for (int p = 0; p < 4; p++) {
                uint32_t ad = kb + swz((uint32_t)(p * 16 + (lane & 7) + ((lane & 16) ? 8 : 0)) * 128
                                       + kc * 32 + ((lane & 8) ? 16 : 0));
                uint32_t r0, r1, r2, r3;
                LDMX4(r0, r1, r2, r3, ad);
                bf[2 * p][0] = r0; bf[2 * p][1] = r1;
                bf[2 * p + 1][0] = r2; bf[2 * p + 1][1] = r3;
            }
            #pragma unroll
            for (int nt = 0; nt < 8; nt++)
                mma_f16(s[nt], qa[kc], bf[nt]);
        }

        uint32_t ph[8][2];
        const uint32_t* mrow = mskh + tile * 32;
        #pragma unroll
        for (int nt = 0; nt < 8; nt++) {
            uint32_t m2 = mrow[nt * 4 + q];
            ph[nt][0] = ex2h2(hadd2u(packh2(s[nt][0], s[nt][1]), m2));
            ph[nt][1] = ex2h2(hadd2u(packh2(s[nt][2], s[nt][3]), m2));
        }

        // lsum via hadd2 trees (off the tensor pipe)
        {
            uint32_t r0 = hadd2u(hadd2u(ph[0][0], ph[1][0]), hadd2u(ph[2][0], ph[3][0]));
            uint32_t r0b = hadd2u(hadd2u(ph[4][0], ph[5][0]), hadd2u(ph[6][0], ph[7][0]));
            r0 = hadd2u(r0, r0b);
            uint32_t r1 = hadd2u(hadd2u(ph[0][1], ph[1][1]), hadd2u(ph[2][1], ph[3][1]));
            uint32_t r1b = hadd2u(hadd2u(ph[4][1], ph[5][1]), hadd2u(ph[6][1], ph[7][1]));
            r1 = hadd2u(r1, r1b);
            float2 f0 = __half22float2(*(__half2*)&r0);
            float2 f1 = __half22float2(*(__half2*)&r1);
            lsum0 += f0.x + f0.y;
            lsum1 += f1.x + f1.y;
        }

        const uint32_t vb = kb + 8192;
        #pragma unroll
        for (int kc = 0; kc < 4; kc++) {
            uint32_t pa[4];
            pa[0] = ph[2 * kc][0];
            pa[1] = ph[2 * kc][1];
            pa[2] = ph[2 * kc + 1][0];
            pa[3] = ph[2 * kc + 1][1];
            uint32_t vf[8][2];
            #pragma unroll
            for (int dp = 0; dp < 4; dp++) {
                uint32_t ad = vb + swz((uint32_t)(kc * 16 + (lane & 7) + ((lane & 8) ? 8 : 0)) * 128
                                       + dp * 32 + ((lane & 16) ? 16 : 0));
                uint32_t r0, r1, r2, r3;
                LDMX4T(r0, r1, r2, r3, ad);
                vf[2 * dp][0] = r0; vf[2 * dp][1] = r1;
                vf[2 * dp + 1][0] = r2; vf[2 * dp + 1][1] = r3;
            }
            #pragma unroll
            for (int dt = 0; dt < 8; dt++)
                mma_f16(o[dt], pa, vf[dt]);
        }
    };

    for (int w = 0; w < NT; w += 4) {
        if (w + 2 < NT) {
            stage_tile(w + 2, 2);
            stage_tile(w + 3, 3);
            CPCOMMIT();
        }
        compute_tile(0, w);
        compute_tile(1, w + 1);
        CPWAIT0();
        __syncthreads();
        if (w + 4 < NT) {
            stage_tile(w + 4, 0);
            stage_tile(w + 5, 1);
            CPCOMMIT();
        }
        compute_tile(2, w + 2);
        compute_tile(3, w + 3);
        CPWAIT0();
        __syncthreads();
    }

    // cross-q reduce (4 lanes share each row), then normalize + store
    lsum0 += __shfl_xor_sync(0xffffffffu, lsum0, 1);
    lsum0 += __shfl_xor_sync(0xffffffffu, lsum0, 2);
    lsum1 += __shfl_xor_sync(0xffffffffu, lsum1, 1);
    lsum1 += __shfl_xor_sync(0xffffffffu, lsum1, 2);
    float i0 = 1.0f / lsum0, i1 = 1.0f / lsum1;
    int s0 = q0 + wq + g;
    int s1 = s0 + 8;
    float* d0 = out + ((size_t)b * SEQ + s0) * DM + h * HDIM;
    float* d1 = out + ((size_t)b * SEQ + s1) * DM + h * HDIM;
    #pragma unroll
    for (int dt = 0; dt < 8; dt++) {
        int col = dt * 8 + 2 * q;
        *(float2*)(d0 + col) = make_float2(o[dt][0] * i0, o[dt][1] * i0);
        *(float2*)(d1 + col) = make_float2(o[dt][2] * i1, o[dt][3] * i1);
    }
}

// ---------------------------------------------------------------------------
extern "C" void kernel_launch(void* const* d_in, const int* in_sizes, int n_in,
                              void* d_out, int out_size)
{
    const float* X    = (const float*)d_in[0];
    const float* mask = (const float*)d_in[1];
    const float* Wq   = (const float*)d_in[2];
    const float* bq   = (const float*)d_in[3];
    const float* Wk   = (const float*)d_in[4];
    const float* bk   = (const float*)d_in[5];
    const float* Wv   = (const float*)d_in[6];
    const float* bv   = (const float*)d_in[7];
    float* out = (float*)d_out;

    static int attr_set = 0;
    if (!attr_set) {
        cudaFuncSetAttribute(qkv_kernel,
                             cudaFuncAttributeMaxDynamicSharedMemorySize, QKV_SMEM);
        cudaFuncSetAttribute(attn_kernel,
                             cudaFuncAttributeMaxDynamicSharedMemorySize, SQ_TOT);
        attr_set = 1;
    }

    f2h_kernel<<<dim3(2048, 4), 256>>>(X, Wq, Wk, Wv);

    dim3 gemm_grid(DM / 128, MTOT / 128, 3);   // (8, 64, 3)
    qkv_kernel<<<gemm_grid, 256, QKV_SMEM>>>(bq, bk, bv);

    dim3 attn_grid(SEQ / 128, NB * NH);        // (16, 64)
    attn_kernel<<<attn_grid, 256, SQ_TOT>>>(mask, out);
}

// round 15
// speedup vs baseline: 1.0500x; 1.0500x over previous
#include <cuda_runtime.h>
#include <cuda_fp16.h>
#include <cstdint>

#define NH   16
#define DM   1024
#define HDIM 64
#define NB   4
#define SEQ  2048
#define MTOT (NB * SEQ)   // 8192

__device__ __half g_Q[NB * NH * SEQ * HDIM];
__device__ __half g_K[NB * NH * SEQ * HDIM];
__device__ __half g_V[NB * NH * SEQ * HDIM];
__device__ __half g_Xh[(size_t)MTOT * DM];
__device__ __half g_Wh[3][(size_t)DM * DM];

#define LOG2E 1.44269504088896f

__device__ __forceinline__ uint32_t smem_u32(const void* p) {
    uint32_t a;
    asm("{ .reg .u64 t; cvta.to.shared.u64 t, %1; cvt.u32.u64 %0, t; }" : "=r"(a) : "l"(p));
    return a;
}
__device__ __forceinline__ void mma_f16(float* c, const uint32_t* a, const uint32_t* b) {
    asm volatile(
        "mma.sync.aligned.m16n8k16.row.col.f32.f16.f16.f32 "
        "{%0,%1,%2,%3},{%4,%5,%6,%7},{%8,%9},{%0,%1,%2,%3};"
        : "+f"(c[0]), "+f"(c[1]), "+f"(c[2]), "+f"(c[3])
        : "r"(a[0]), "r"(a[1]), "r"(a[2]), "r"(a[3]), "r"(b[0]), "r"(b[1]));
}
#define LDMX4(r0,r1,r2,r3,addr) \
    asm volatile("ldmatrix.sync.aligned.m8n8.x4.shared.b16 {%0,%1,%2,%3}, [%4];" \
        : "=r"(r0),"=r"(r1),"=r"(r2),"=r"(r3) : "r"(addr))
#define LDMX4T(r0,r1,r2,r3,addr) \
    asm volatile("ldmatrix.sync.aligned.m8n8.x4.trans.shared.b16 {%0,%1,%2,%3}, [%4];" \
        : "=r"(r0),"=r"(r1),"=r"(r2),"=r"(r3) : "r"(addr))
#define CP16(dst, src) \
    asm volatile("cp.async.cg.shared.global [%0], [%1], 16;" :: "r"(dst), "l"(src))
#define CPCOMMIT() asm volatile("cp.async.commit_group;" ::: "memory")
#define CPWAIT0()  asm volatile("cp.async.wait_group 0;" ::: "memory")
#define CPWAIT1()  asm volatile("cp.async.wait_group 1;" ::: "memory")

__device__ __forceinline__ uint32_t packh2(float x, float y) {
    __half2 h = __floats2half2_rn(x, y);
    return *(uint32_t*)&h;
}
__device__ __forceinline__ uint32_t ex2h2(uint32_t x) {
    uint32_t y;
    asm("ex2.approx.f16x2 %0, %1;" : "=r"(y) : "r"(x));
    return y;
}
__device__ __forceinline__ uint32_t hadd2u(uint32_t a, uint32_t b) {
    uint32_t y;
    asm("add.f16x2 %0, %1, %2;" : "=r"(y) : "r"(a), "r"(b));
    return y;
}
__device__ __forceinline__ uint32_t swz(uint32_t o) { return o ^ ((o >> 3) & 0x70); }

// ======================= fp32 -> fp16 conversion (16 elems/thread) =====
__global__ __launch_bounds__(256) void f2h_kernel(
    const float* __restrict__ X, const float* __restrict__ Wq,
    const float* __restrict__ Wk, const float* __restrict__ Wv)
{
    int y = blockIdx.y;
    const float* src; __half* dst; size_t n;
    if (y == 0)      { src = X;  dst = g_Xh;    n = (size_t)MTOT * DM; }
    else if (y == 1) { src = Wq; dst = g_Wh[0]; n = (size_t)DM * DM; }
    else if (y == 2) { src = Wk; dst = g_Wh[1]; n = (size_t)DM * DM; }
    else             { src = Wv; dst = g_Wh[2]; n = (size_t)DM * DM; }
    size_t i = ((size_t)blockIdx.x * 256 + threadIdx.x) * 16;
    if (i >= n) return;
    float4 a = *(const float4*)(src + i);
    float4 b = *(const float4*)(src + i + 4);
    float4 c = *(const float4*)(src + i + 8);
    float4 d = *(const float4*)(src + i + 12);
    uint4 u0, u1;
    u0.x = packh2(a.x, a.y); u0.y = packh2(a.z, a.w);
    u0.z = packh2(b.x, b.y); u0.w = packh2(b.z, b.w);
    u1.x = packh2(c.x, c.y); u1.y = packh2(c.z, c.w);
    u1.z = packh2(d.x, d.y); u1.w = packh2(d.z, d.w);
    *(uint4*)(dst + i)     = u0;
    *(uint4*)(dst + i + 8) = u1;
}

// ======================= QKV GEMM: 3-stage cp.async + occupancy 2 ======
#define ROWA 40
#define ROWB 136
#define ABUF (128 * ROWA * 2)
#define BBUF (32 * ROWB * 2)
#define QKV_SMEM (3 * (ABUF + BBUF))
#define KITERS (DM / 32)

__global__ __launch_bounds__(256, 2) void qkv_kernel(
    const float* __restrict__ bq, const float* __restrict__ bk,
    const float* __restrict__ bv)
{
    extern __shared__ __half qsm[];
    __half* Ash = qsm;
    __half* Bsh = qsm + 3 * 128 * ROWA;

    const int z = blockIdx.z;
    const __half* Xh = g_Xh;
    const __half* W  = g_Wh[z];
    const float* bias = (z == 0) ? bq : (z == 1) ? bk : bv;
    __half* out = (z == 0) ? g_Q : (z == 1) ? g_K : g_V;
    const float osc = (z == 0) ? (0.125f * LOG2E) : 1.0f;

    const int t = threadIdx.x, lane = t & 31, wid = t >> 5;
    const int wm = (wid >> 2) * 64, wn = (wid & 3) * 32;
    const int g = lane >> 2, q = lane & 3;
    const int n0 = blockIdx.x * 128, m0 = blockIdx.y * 128;

    float c[4][4][4] = {};

    const __half* aptr = Xh + (size_t)(m0 + (t >> 1)) * DM + (t & 1) * 16;
    const __half* bptr = W + (size_t)(t >> 3) * DM + n0 + (t & 7) * 16;
    const uint32_t ast = smem_u32(Ash) + (uint32_t)(t >> 1) * (ROWA * 2) + (t & 1) * 32;
    const uint32_t bst = smem_u32(Bsh) + (uint32_t)(t >> 3) * (ROWB * 2) + (t & 7) * 32;

    const uint32_t Ab = smem_u32(Ash), Bb = smem_u32(Bsh);
    const uint32_t a_ad0 = Ab + (uint32_t)(wm + (lane & 15)) * (ROWA * 2) + ((lane & 16) ? 16 : 0);
    const uint32_t b_ad0 = Bb + (uint32_t)((lane & 7) + ((lane & 8) ? 8 : 0)) * (ROWB * 2)
                              + (uint32_t)(wn + ((lane & 16) ? 8 : 0)) * 2;

    #pragma unroll
    for (int pg = 0; pg < 2; pg++) {
        const char* asrc = (const char*)(aptr + pg * 32);
        const char* bsrc = (const char*)(bptr + (size_t)(pg * 32) * DM);
        CP16(ast + pg * ABUF, asrc);      CP16(ast + pg * ABUF + 16, asrc + 16);
        CP16(bst + pg * BBUF, bsrc);      CP16(bst + pg * BBUF + 16, bsrc + 16);
        CPCOMMIT();
    }
    CPWAIT1();
    __syncthreads();

    for (int it = 0; it < KITERS; it++) {
        const int cur = it % 3;
        if (it + 2 < KITERS) {
            const int sl = (it + 2) % 3;
            const char* asrc = (const char*)(aptr + (it + 2) * 32);
            const char* bsrc = (const char*)(bptr + (size_t)(it + 2) * 32 * DM);
            CP16(ast + sl * ABUF, asrc);      CP16(ast + sl * ABUF + 16, asrc + 16);
            CP16(bst + sl * BBUF, bsrc);      CP16(bst + sl * BBUF + 16, bsrc + 16);
            CPCOMMIT();
        }

        const uint32_t a_ad = a_ad0 + cur * ABUF;
        const uint32_t b_ad = b_ad0 + cur * BBUF;
        #pragma unroll
        for (int kc = 0; kc < 2; kc++) {
            uint32_t af[4][4];
            #pragma unroll
            for (int mt = 0; mt < 4; mt++)
                LDMX4(af[mt][0], af[mt][1], af[mt][2], af[mt][3],
                      a_ad + (uint32_t)mt * 16 * (ROWA * 2) + kc * 32);
            uint32_t bf[4][2];
            #pragma unroll
            for (int p = 0; p < 2; p++) {
                uint32_t r0, r1, r2, r3;
                LDMX4T(r0, r1, r2, r3,
                       b_ad + (uint32_t)kc * 16 * (ROWB * 2) + p * 32);
                bf[2 * p][0] = r0; bf[2 * p][1] = r1;
                bf[2 * p + 1][0] = r2; bf[2 * p + 1][1] = r3;
            }
            #pragma unroll
            for (int mt = 0; mt < 4; mt++)
                #pragma unroll
                for (int nt = 0; nt < 4; nt++)
                    mma_f16(c[mt][nt], af[mt], bf[nt]);
        }

        if (it + 2 < KITERS) CPWAIT1(); else CPWAIT0();
        __syncthreads();
    }

    #pragma unroll
    for (int nt = 0; nt < 4; nt++) {
        int n = n0 + wn + nt * 8 + 2 * q;
        int h = n >> 6, hd = n & 63;
        float bx = bias[n], by = bias[n + 1];
        #pragma unroll
        for (int mt = 0; mt < 4; mt++) {
            int m = m0 + wm + mt * 16 + g;
            int b0i = m >> 11, s0i = m & 2047;
            int b1i = (m + 8) >> 11, s1i = (m + 8) & 2047;
            __half2 r0 = __floats2half2_rn((c[mt][nt][0] + bx) * osc, (c[mt][nt][1] + by) * osc);
            __half2 r1 = __floats2half2_rn((c[mt][nt][2] + bx) * osc, (c[mt][nt][3] + by) * osc);
            *(__half2*)&out[((size_t)(b0i * NH + h) * SEQ + s0i) * HDIM + hd] = r0;
            *(__half2*)&out[((size_t)(b1i * NH + h) * SEQ + s1i) * HDIM + hd] = r1;
        }
    }
}

// ======================= Flash attention: hadd2 lsum, hoisted mask =====
#define SQ_Q    0
#define SQ_KV   16384                  // 4 stages x (K 8KB + V 8KB)
#define SQ_MSK  (16384 + 4 * 16384)    // 81920; [NT][32] u32 = 4 KB
#define SQ_TOT  (81920 + 4096)
#define NT      (SEQ / 64)

__global__ __launch_bounds__(256, 2) void attn_kernel(
    const float* __restrict__ mask,  // [B,S]
    float* __restrict__ out)         // [B,S,D]
{
    extern __shared__ char sm[];
    const uint32_t sb = smem_u32(sm);
    const int t = threadIdx.x, lane = t & 31, wid = t >> 5;
    const int g = lane >> 2, q = lane & 3;
    const int wq = wid * 16;

    const int bh = blockIdx.y;
    const int b = bh >> 4, h = bh & 15;
    const int q0 = blockIdx.x * 128;

    const __half* Qg = g_Q + (size_t)bh * SEQ * HDIM + (size_t)q0 * HDIM;
    const __half* Kg = g_K + (size_t)bh * SEQ * HDIM;
    const __half* Vg = g_V + (size_t)bh * SEQ * HDIM;
    const float* mk = mask + (size_t)b * SEQ;
    uint32_t* mskh = (uint32_t*)(sm + SQ_MSK);   // [NT][32] half2, *LOG2E

    const int kr = t >> 3, kj = t & 7;
    const uint32_t koffA = swz((uint32_t)kr * 128 + kj * 16);
    const uint32_t koffB = swz((uint32_t)(kr + 32) * 128 + kj * 16);

    auto stage_tile = [&](int tile, const int st) {
        const uint32_t kb = sb + SQ_KV + (uint32_t)st * 16384;
        const char* ksA = (const char*)(Kg + ((size_t)tile * 64 + kr) * HDIM) + kj * 16;
        const char* ksB = (const char*)(Kg + ((size_t)tile * 64 + kr + 32) * HDIM) + kj * 16;
        const char* vsA = (const char*)(Vg + ((size_t)tile * 64 + kr) * HDIM) + kj * 16;
        const char* vsB = (const char*)(Vg + ((size_t)tile * 64 + kr + 32) * HDIM) + kj * 16;
        CP16(kb + koffA, ksA);
        CP16(kb + koffB, ksB);
        CP16(kb + 8192 + koffA, vsA);
        CP16(kb + 8192 + koffB, vsB);
    };

    stage_tile(0, 0);
    stage_tile(1, 1);
    CPCOMMIT();
    {   // stage Q
        int r = t >> 1;
        const uint4* src = (const uint4*)(Qg + (size_t)r * HDIM) + (t & 1) * 4;
        #pragma unroll
        for (int j = 0; j < 4; j++)
            *(uint4*)(sm + SQ_Q + swz((uint32_t)r * 128 + ((t & 1) * 4 + j) * 16)) = src[j];
    }
    {   // pre-stage whole mask row
        #pragma unroll
        for (int j = 0; j < 4; j++) {
            int e = t + j * 256;
            mskh[e] = packh2(mk[2 * e] * LOG2E, mk[2 * e + 1] * LOG2E);
        }
    }
    CPWAIT0();
    __syncthreads();

    uint32_t qa[4][4];
    #pragma unroll
    for (int kc = 0; kc < 4; kc++) {
        uint32_t ad = sb + SQ_Q + swz((uint32_t)(wq + (lane & 15)) * 128
                                      + kc * 32 + ((lane & 16) ? 16 : 0));
        LDMX4(qa[kc][0], qa[kc][1], qa[kc][2], qa[kc][3], ad);
    }

    float o[8][4] = {};
    float lsum0 = 0.0f, lsum1 = 0.0f;

    auto compute_tile = [&](const int st, const int tile) {
        const uint32_t kb = sb + SQ_KV + (uint32_t)st * 16384;
        float s[8][4] = {};
        #pragma unroll
        for (int kc = 0; kc < 4; kc++) {
            uint32_t bf[8][2];
            #pragma unroll
            for (int p = 0; p < 4; p++) {
                uint32_t ad = kb + swz((uint32_t)(p * 16 + (lane & 7) + ((lane & 16) ? 8 : 0)) * 128
                                       + kc * 32 + ((lane & 8) ? 16 : 0));
                uint32_t r0, r1, r2, r3;
                LDMX4(r0, r1, r2, r3, ad);
                bf[2 * p][0] = r0; bf[2 * p][1] = r1;
                bf[2 * p + 1][0] = r2; bf[2 * p + 1][1] = r3;
            }
            #pragma unroll
            for (int nt = 0; nt < 8; nt++)
                mma_f16(s[nt], qa[kc], bf[nt]);
        }

        uint32_t ph[8][2];
        const uint32_t* mrow = mskh + tile * 32;
        #pragma unroll
        for (int nt = 0; nt < 8; nt++) {
            uint32_t m2 = mrow[nt * 4 + q];
            ph[nt][0] = ex2h2(hadd2u(packh2(s[nt][0], s[nt][1]), m2));
            ph[nt][1] = ex2h2(hadd2u(packh2(s[nt][2], s[nt][3]), m2));
        }

        {
            uint32_t r0 = hadd2u(hadd2u(ph[0][0], ph[1][0]), hadd2u(ph[2][0], ph[3][0]));
            uint32_t r0b = hadd2u(hadd2u(ph[4][0], ph[5][0]), hadd2u(ph[6][0], ph[7][0]));
            r0 = hadd2u(r0, r0b);
            uint32_t r1 = hadd2u(hadd2u(ph[0][1], ph[1][1]), hadd2u(ph[2][1], ph[3][1]));
            uint32_t r1b = hadd2u(hadd2u(ph[4][1], ph[5][1]), hadd2u(ph[6][1], ph[7][1]));
            r1 = hadd2u(r1, r1b);
            float2 f0 = __half22float2(*(__half2*)&r0);
            float2 f1 = __half22float2(*(__half2*)&r1);
            lsum0 += f0.x + f0.y;
            lsum1 += f1.x + f1.y;
        }

        const uint32_t vb = kb + 8192;
        #pragma unroll
        for (int kc = 0; kc < 4; kc++) {
            uint32_t pa[4];
            pa[0] = ph[2 * kc][0];
            pa[1] = ph[2 * kc][1];
            pa[2] = ph[2 * kc + 1][0];
            pa[3] = ph[2 * kc + 1][1];
            uint32_t vf[8][2];
            #pragma unroll
            for (int dp = 0; dp < 4; dp++) {
                uint32_t ad = vb + swz((uint32_t)(kc * 16 + (lane & 7) + ((lane & 8) ? 8 : 0)) * 128
                                       + dp * 32 + ((lane & 16) ? 16 : 0));
                uint32_t r0, r1, r2, r3;
                LDMX4T(r0, r1, r2, r3, ad);
                vf[2 * dp][0] = r0; vf[2 * dp][1] = r1;
                vf[2 * dp + 1][0] = r2; vf[2 * dp + 1][1] = r3;
            }
            #pragma unroll
            for (int dt = 0; dt < 8; dt++)
                mma_f16(o[dt], pa, vf[dt]);
        }
    };

    for (int w = 0; w < NT; w += 4) {
        if (w + 2 < NT) {
            stage_tile(w + 2, 2);
            stage_tile(w + 3, 3);
            CPCOMMIT();
        }
        compute_tile(0, w);
        compute_tile(1, w + 1);
        CPWAIT0();
        __syncthreads();
        if (w + 4 < NT) {
            stage_tile(w + 4, 0);
            stage_tile(w + 5, 1);
            CPCOMMIT();
        }
        compute_tile(2, w + 2);
        compute_tile(3, w + 3);
        CPWAIT0();
        __syncthreads();
    }

    lsum0 += __shfl_xor_sync(0xffffffffu, lsum0, 1);
    lsum0 += __shfl_xor_sync(0xffffffffu, lsum0, 2);
    lsum1 += __shfl_xor_sync(0xffffffffu, lsum1, 1);
    lsum1 += __shfl_xor_sync(0xffffffffu, lsum1, 2);
    float i0 = 1.0f / lsum0, i1 = 1.0f / lsum1;
    int s0 = q0 + wq + g;
    int s1 = s0 + 8;
    float* d0 = out + ((size_t)b * SEQ + s0) * DM + h * HDIM;
    float* d1 = out + ((size_t)b * SEQ + s1) * DM + h * HDIM;
    #pragma unroll
    for (int dt = 0; dt < 8; dt++) {
        int col = dt * 8 + 2 * q;
        *(float2*)(d0 + col) = make_float2(o[dt][0] * i0, o[dt][1] * i0);
        *(float2*)(d1 + col) = make_float2(o[dt][2] * i1, o[dt][3] * i1);
    }
}

// ---------------------------------------------------------------------------
extern "C" void kernel_launch(void* const* d_in, const int* in_sizes, int n_in,
                              void* d_out, int out_size)
{
    const float* X    = (const float*)d_in[0];
    const float* mask = (const float*)d_in[1];
    const float* Wq   = (const float*)d_in[2];
    const float* bq   = (const float*)d_in[3];
    const float* Wk   = (const float*)d_in[4];
    const float* bk   = (const float*)d_in[5];
    const float* Wv   = (const float*)d_in[6];
    const float* bv   = (const float*)d_in[7];
    float* out = (float*)d_out;

    static int attr_set = 0;
    if (!attr_set) {
        cudaFuncSetAttribute(qkv_kernel,
                             cudaFuncAttributeMaxDynamicSharedMemorySize, QKV_SMEM);
        cudaFuncSetAttribute(attn_kernel,
                             cudaFuncAttributeMaxDynamicSharedMemorySize, SQ_TOT);
        attr_set = 1;
    }

    f2h_kernel<<<dim3(2048, 4), 256>>>(X, Wq, Wk, Wv);

    dim3 gemm_grid(DM / 128, MTOT / 128, 3);   // (8, 64, 3)
    qkv_kernel<<<gemm_grid, 256, QKV_SMEM>>>(bq, bk, bv);

    dim3 attn_grid(SEQ / 128, NB * NH);        // (16, 64)
    attn_kernel<<<attn_grid, 256, SQ_TOT>>>(mask, out);
}

// round 16
// speedup vs baseline: 1.0930x; 1.0409x over previous
#include <cuda_runtime.h>
#include <cuda_fp16.h>
#include <cstdint>

#define NH   16
#define DM   1024
#define HDIM 64
#define NB   4
#define SEQ  2048
#define MTOT (NB * SEQ)   // 8192

__device__ __half g_Q[NB * NH * SEQ * HDIM];
__device__ __half g_K[NB * NH * SEQ * HDIM];
__device__ __half g_V[NB * NH * SEQ * HDIM];
__device__ __half g_Xh[(size_t)MTOT * DM];
__device__ __half g_Wh[3][(size_t)DM * DM];

#define LOG2E 1.44269504088896f

__device__ __forceinline__ uint32_t smem_u32(const void* p) {
    uint32_t a;
    asm("{ .reg .u64 t; cvta.to.shared.u64 t, %1; cvt.u32.u64 %0, t; }" : "=r"(a) : "l"(p));
    return a;
}
__device__ __forceinline__ void mma_f16(float* c, const uint32_t* a, const uint32_t* b) {
    asm volatile(
        "mma.sync.aligned.m16n8k16.row.col.f32.f16.f16.f32 "
        "{%0,%1,%2,%3},{%4,%5,%6,%7},{%8,%9},{%0,%1,%2,%3};"
        : "+f"(c[0]), "+f"(c[1]), "+f"(c[2]), "+f"(c[3])
        : "r"(a[0]), "r"(a[1]), "r"(a[2]), "r"(a[3]), "r"(b[0]), "r"(b[1]));
}
#define LDMX4(r0,r1,r2,r3,addr) \
    asm volatile("ldmatrix.sync.aligned.m8n8.x4.shared.b16 {%0,%1,%2,%3}, [%4];" \
        : "=r"(r0),"=r"(r1),"=r"(r2),"=r"(r3) : "r"(addr))
#define LDMX4T(r0,r1,r2,r3,addr) \
    asm volatile("ldmatrix.sync.aligned.m8n8.x4.trans.shared.b16 {%0,%1,%2,%3}, [%4];" \
        : "=r"(r0),"=r"(r1),"=r"(r2),"=r"(r3) : "r"(addr))
#define CP16(dst, src) \
    asm volatile("cp.async.cg.shared.global [%0], [%1], 16;" :: "r"(dst), "l"(src))
#define CPCOMMIT() asm volatile("cp.async.commit_group;" ::: "memory")
#define CPWAIT0()  asm volatile("cp.async.wait_group 0;" ::: "memory")
#define CPWAIT1()  asm volatile("cp.async.wait_group 1;" ::: "memory")

__device__ __forceinline__ uint32_t packh2(float x, float y) {
    __half2 h = __floats2half2_rn(x, y);
    return *(uint32_t*)&h;
}
__device__ __forceinline__ uint32_t ex2h2(uint32_t x) {
    uint32_t y;
    asm("ex2.approx.f16x2 %0, %1;" : "=r"(y) : "r"(x));
    return y;
}
__device__ __forceinline__ uint32_t hadd2u(uint32_t a, uint32_t b) {
    uint32_t y;
    asm("add.f16x2 %0, %1, %2;" : "=r"(y) : "r"(a), "r"(b));
    return y;
}
__device__ __forceinline__ uint32_t swz(uint32_t o) { return o ^ ((o >> 3) & 0x70); }

// ======================= fp32 -> fp16 conversion (16 elems/thread) =====
__global__ __launch_bounds__(256) void f2h_kernel(
    const float* __restrict__ X, const float* __restrict__ Wq,
    const float* __restrict__ Wk, const float* __restrict__ Wv)
{
    int y = blockIdx.y;
    const float* src; __half* dst; size_t n;
    if (y == 0)      { src = X;  dst = g_Xh;    n = (size_t)MTOT * DM; }
    else if (y == 1) { src = Wq; dst = g_Wh[0]; n = (size_t)DM * DM; }
    else if (y == 2) { src = Wk; dst = g_Wh[1]; n = (size_t)DM * DM; }
    else             { src = Wv; dst = g_Wh[2]; n = (size_t)DM * DM; }
    size_t i = ((size_t)blockIdx.x * 256 + threadIdx.x) * 16;
    if (i >= n) return;
    float4 a = *(const float4*)(src + i);
    float4 b = *(const float4*)(src + i + 4);
    float4 c = *(const float4*)(src + i + 8);
    float4 d = *(const float4*)(src + i + 12);
    uint4 u0, u1;
    u0.x = packh2(a.x, a.y); u0.y = packh2(a.z, a.w);
    u0.z = packh2(b.x, b.y); u0.w = packh2(b.z, b.w);
    u1.x = packh2(c.x, c.y); u1.y = packh2(c.z, c.w);
    u1.z = packh2(d.x, d.y); u1.w = packh2(d.z, d.w);
    *(uint4*)(dst + i)     = u0;
    *(uint4*)(dst + i + 8) = u1;
}

// ======================= QKV GEMM: 3-stage, unrolled literal stages ====
#define ROWA 40
#define ROWB 136
#define ABUF (128 * ROWA * 2)
#define BBUF (32 * ROWB * 2)
#define QKV_SMEM (3 * (ABUF + BBUF))
#define KITERS (DM / 32)

__global__ __launch_bounds__(256, 2) void qkv_kernel(
    const float* __restrict__ bq, const float* __restrict__ bk,
    const float* __restrict__ bv)
{
    extern __shared__ __half qsm[];
    __half* Ash = qsm;
    __half* Bsh = qsm + 3 * 128 * ROWA;

    const int z = blockIdx.z;
    const __half* Xh = g_Xh;
    const __half* W  = g_Wh[z];
    const float* bias = (z == 0) ? bq : (z == 1) ? bk : bv;
    __half* out = (z == 0) ? g_Q : (z == 1) ? g_K : g_V;
    const float osc = (z == 0) ? (0.125f * LOG2E) : 1.0f;

    const int t = threadIdx.x, lane = t & 31, wid = t >> 5;
    const int wm = (wid >> 2) * 64, wn = (wid & 3) * 32;
    const int g = lane >> 2, q = lane & 3;
    const int n0 = blockIdx.x * 128, m0 = blockIdx.y * 128;

    float c[4][4][4] = {};

    const __half* aptr = Xh + (size_t)(m0 + (t >> 1)) * DM + (t & 1) * 16;
    const __half* bptr = W + (size_t)(t >> 3) * DM + n0 + (t & 7) * 16;
    const uint32_t ast = smem_u32(Ash) + (uint32_t)(t >> 1) * (ROWA * 2) + (t & 1) * 32;
    const uint32_t bst = smem_u32(Bsh) + (uint32_t)(t >> 3) * (ROWB * 2) + (t & 7) * 32;

    const uint32_t Ab = smem_u32(Ash), Bb = smem_u32(Bsh);
    const uint32_t a_ad0 = Ab + (uint32_t)(wm + (lane & 15)) * (ROWA * 2) + ((lane & 16) ? 16 : 0);
    const uint32_t b_ad0 = Bb + (uint32_t)((lane & 7) + ((lane & 8) ? 8 : 0)) * (ROWB * 2)
                              + (uint32_t)(wn + ((lane & 16) ? 8 : 0)) * 2;

    // st literal at call sites -> addressing folds
    auto stage_slab = [&](int it, const int st) {
        const char* asrc = (const char*)(aptr + it * 32);
        const char* bsrc = (const char*)(bptr + (size_t)it * 32 * DM);
        CP16(ast + st * ABUF, asrc);      CP16(ast + st * ABUF + 16, asrc + 16);
        CP16(bst + st * BBUF, bsrc);      CP16(bst + st * BBUF + 16, bsrc + 16);
    };
    auto compute_slab = [&](const int st) {
        const uint32_t a_ad = a_ad0 + st * ABUF;
        const uint32_t b_ad = b_ad0 + st * BBUF;
        #pragma unroll
        for (int kc = 0; kc < 2; kc++) {
            uint32_t af[4][4];
            #pragma unroll
            for (int mt = 0; mt < 4; mt++)
                LDMX4(af[mt][0], af[mt][1], af[mt][2], af[mt][3],
                      a_ad + (uint32_t)mt * 16 * (ROWA * 2) + kc * 32);
            uint32_t bf[4][2];
            #pragma unroll
            for (int p = 0; p < 2; p++) {
                uint32_t r0, r1, r2, r3;
                LDMX4T(r0, r1, r2, r3,
                       b_ad + (uint32_t)kc * 16 * (ROWB * 2) + p * 32);
                bf[2 * p][0] = r0; bf[2 * p][1] = r1;
                bf[2 * p + 1][0] = r2; bf[2 * p + 1][1] = r3;
            }
            #pragma unroll
            for (int mt = 0; mt < 4; mt++)
                #pragma unroll
                for (int nt = 0; nt < 4; nt++)
                    mma_f16(c[mt][nt], af[mt], bf[nt]);
        }
    };
    // one pipeline step, identical cadence to R15 (commit -> wait1 -> sync)
    auto step = [&](int it, const int cur, const int sl) {
        if (it + 2 < KITERS) {
            stage_slab(it + 2, sl);
            CPCOMMIT();
        }
        compute_slab(cur);
        if (it + 2 < KITERS) CPWAIT1(); else CPWAIT0();
        __syncthreads();
    };

    // prologue: slabs 0,1 into stages 0,1
    stage_slab(0, 0);
    CPCOMMIT();
    stage_slab(1, 1);
    CPCOMMIT();
    CPWAIT1();
    __syncthreads();

    // 30 iterations unrolled by 3 with literal stages, then literal tail
    for (int it = 0; it < KITERS - 2; it += 3) {
        step(it,     0, 2);
        step(it + 1, 1, 0);
        step(it + 2, 2, 1);
    }
    step(KITERS - 2, 0, 2);   // it=30: no prefetch, wait0
    step(KITERS - 1, 1, 0);   // it=31

    #pragma unroll
    for (int nt = 0; nt < 4; nt++) {
        int n = n0 + wn + nt * 8 + 2 * q;
        int h = n >> 6, hd = n & 63;
        float bx = bias[n], by = bias[n + 1];
        #pragma unroll
        for (int mt = 0; mt < 4; mt++) {
            int m = m0 + wm + mt * 16 + g;
            int b0i = m >> 11, s0i = m & 2047;
            int b1i = (m + 8) >> 11, s1i = (m + 8) & 2047;
            __half2 r0 = __floats2half2_rn((c[mt][nt][0] + bx) * osc, (c[mt][nt][1] + by) * osc);
            __half2 r1 = __floats2half2_rn((c[mt][nt][2] + bx) * osc, (c[mt][nt][3] + by) * osc);
            *(__half2*)&out[((size_t)(b0i * NH + h) * SEQ + s0i) * HDIM + hd] = r0;
            *(__half2*)&out[((size_t)(b1i * NH + h) * SEQ + s1i) * HDIM + hd] = r1;
        }
    }
}

// ======================= Flash attention (frozen R14/R15 best) =========
#define SQ_Q    0
#define SQ_KV   16384
#define SQ_MSK  (16384 + 4 * 16384)
#define SQ_TOT  (81920 + 4096)
#define NT      (SEQ / 64)

__global__ __launch_bounds__(256, 2) void attn_kernel(
    const float* __restrict__ mask,  // [B,S]
    float* __restrict__ out)         // [B,S,D]
{
    extern __shared__ char sm[];
    const uint32_t sb = smem_u32(sm);
    const int t = threadIdx.x, lane = t & 31, wid = t >> 5;
    const int g = lane >> 2, q = lane & 3;
    const int wq = wid * 16;

    const int bh = blockIdx.y;
    const int b = bh >> 4, h = bh & 15;
    const int q0 = blockIdx.x * 128;

    const __half* Qg = g_Q + (size_t)bh * SEQ * HDIM + (size_t)q0 * HDIM;
    const __half* Kg = g_K + (size_t)bh * SEQ * HDIM;
    const __half* Vg = g_V + (size_t)bh * SEQ * HDIM;
    const float* mk = mask + (size_t)b * SEQ;
    uint32_t* mskh = (uint32_t*)(sm + SQ_MSK);

    const int kr = t >> 3, kj = t & 7;
    const uint32_t koffA = swz((uint32_t)kr * 128 + kj * 16);
    const uint32_t koffB = swz((uint32_t)(kr + 32) * 128 + kj * 16);

    auto stage_tile = [&](int tile, const int st) {
        const uint32_t kb = sb + SQ_KV + (uint32_t)st * 16384;
        const char* ksA = (const char*)(Kg + ((size_t)tile * 64 + kr) * HDIM) + kj * 16;
        const char* ksB = (const char*)(Kg + ((size_t)tile * 64 + kr + 32) * HDIM) + kj * 16;
        const char* vsA = (const char*)(Vg + ((size_t)tile * 64 + kr) * HDIM) + kj * 16;
        const char* vsB = (const char*)(Vg + ((size_t)tile * 64 + kr + 32) * HDIM) + kj * 16;
        CP16(kb + koffA, ksA);
        CP16(kb + koffB, ksB);
        CP16(kb + 8192 + koffA, vsA);
        CP16(kb + 8192 + koffB, vsB);
    };

    stage_tile(0, 0);
    stage_tile(1, 1);
    CPCOMMIT();
    {
        int r = t >> 1;
        const uint4* src = (const uint4*)(Qg + (size_t)r * HDIM) + (t & 1) * 4;
        #pragma unroll
        for (int j = 0; j < 4; j++)
            *(uint4*)(sm + SQ_Q + swz((uint32_t)r * 128 + ((t & 1) * 4 + j) * 16)) = src[j];
    }
    {
        #pragma unroll
        for (int j = 0; j < 4; j++) {
            int e = t + j * 256;
            mskh[e] = packh2(mk[2 * e] * LOG2E, mk[2 * e + 1] * LOG2E);
        }
    }
    CPWAIT0();
    __syncthreads();

    uint32_t qa[4][4];
    #pragma unroll
    for (int kc = 0; kc < 4; kc++) {
        uint32_t ad = sb + SQ_Q + swz((uint32_t)(wq + (lane & 15)) * 128
                                      + kc * 32 + ((lane & 16) ? 16 : 0));
        LDMX4(qa[kc][0], qa[kc][1], qa[kc][2], qa[kc][3], ad);
    }

    float o[8][4] = {};
    float lsum0 = 0.0f, lsum1 = 0.0f;

    auto compute_tile = [&](const int st, const int tile) {
        const uint32_t kb = sb + SQ_KV + (uint32_t)st * 16384;
        float s[8][4] = {};
        #pragma unroll
        for (int kc = 0; kc < 4; kc++) {
            uint32_t bf[8][2];
            #pragma unroll
            for (int p = 0; p < 4; p++) {
                uint32_t ad = kb + swz((uint32_t)(p * 16 + (lane & 7) + ((lane & 16) ? 8 : 0)) * 128
                                       + kc * 32 + ((lane & 8) ? 16 : 0));
                uint32_t r0, r1, r2, r3;
                LDMX4(r0, r1, r2, r3, ad);
                bf[2 * p][0] = r0; bf[2 * p][1] = r1;
                bf[2 * p + 1][0] = r2; bf[2 * p + 1][1] = r3;
            }
            #pragma unroll
            for (int nt = 0; nt < 8; nt++)
                mma_f16(s[nt], qa[kc], bf[nt]);
        }

        uint32_t ph[8][2];
        const uint32_t* mrow = mskh + tile * 32;
        #pragma unroll
        for (int nt = 0; nt < 8; nt++) {
            uint32_t m2 = mrow[nt * 4 + q];
            ph[nt][0] = ex2h2(hadd2u(packh2(s[nt][0], s[nt][1]), m2));
            ph[nt][1] = ex2h2(hadd2u(packh2(s[nt][2], s[nt][3]), m2));
        }

        {
            uint32_t r0 = hadd2u(hadd2u(ph[0][0], ph[1][0]), hadd2u(ph[2][0], ph[3][0]));
            uint32_t r0b = hadd2u(hadd2u(ph[4][0], ph[5][0]), hadd2u(ph[6][0], ph[7][0]));
            r0 = hadd2u(r0, r0b);
            uint32_t r1 = hadd2u(hadd2u(ph[0][1], ph[1][1]), hadd2u(ph[2][1], ph[3][1]));
            uint32_t r1b = hadd2u(hadd2u(ph[4][1], ph[5][1]), hadd2u(ph[6][1], ph[7][1]));
            r1 = hadd2u(r1, r1b);
            float2 f0 = __half22float2(*(__half2*)&r0);
            float2 f1 = __half22float2(*(__half2*)&r1);
            lsum0 += f0.x + f0.y;
            lsum1 += f1.x + f1.y;
        }

        const uint32_t vb = kb + 8192;
        #pragma unroll
        for (int kc = 0; kc < 4; kc++) {
            uint32_t pa[4];
            pa[0] = ph[2 * kc][0];
            pa[1] = ph[2 * kc][1];
            pa[2] = ph[2 * kc + 1][0];
            pa[3] = ph[2 * kc + 1][1];
            uint32_t vf[8][2];
            #pragma unroll
            for (int dp = 0; dp < 4; dp++) {
                uint32_t ad = vb + swz((uint32_t)(kc * 16 + (lane & 7) + ((lane & 8) ? 8 : 0)) * 128
                                       + dp * 32 + ((lane & 16) ? 16 : 0));
                uint32_t r0, r1, r2, r3;
                LDMX4T(r0, r1, r2, r3, ad);
                vf[2 * dp][0] = r0; vf[2 * dp][1] = r1;
                vf[2 * dp + 1][0] = r2; vf[2 * dp + 1][1] = r3;
            }
            #pragma unroll
            for (int dt = 0; dt < 8; dt++)
                mma_f16(o[dt], pa, vf[dt]);
        }
    };

    for (int w = 0; w < NT; w += 4) {
        if (w + 2 < NT) {
            stage_tile(w + 2, 2);
            stage_tile(w + 3, 3);
            CPCOMMIT();
        }
        compute_tile(0, w);
        compute_tile(1, w + 1);
        CPWAIT0();
        __syncthreads();
        if (w + 4 < NT) {
            stage_tile(w + 4, 0);
            stage_tile(w + 5, 1);
            CPCOMMIT();
        }
        compute_tile(2, w + 2);
        compute_tile(3, w + 3);
        CPWAIT0();
        __syncthreads();
    }

    lsum0 += __shfl_xor_sync(0xffffffffu, lsum0, 1);
    lsum0 += __shfl_xor_sync(0xffffffffu, lsum0, 2);
    lsum1 += __shfl_xor_sync(0xffffffffu, lsum1, 1);
    lsum1 += __shfl_xor_sync(0xffffffffu, lsum1, 2);
    float i0 = 1.0f / lsum0, i1 = 1.0f / lsum1;
    int s0 = q0 + wq + g;
    int s1 = s0 + 8;
    float* d0 = out + ((size_t)b * SEQ + s0) * DM + h * HDIM;
    float* d1 = out + ((size_t)b * SEQ + s1) * DM + h * HDIM;
    #pragma unroll
    for (int dt = 0; dt < 8; dt++) {
        int col = dt * 8 + 2 * q;
        *(float2*)(d0 + col) = make_float2(o[dt][0] * i0, o[dt][1] * i0);
        *(float2*)(d1 + col) = make_float2(o[dt][2] * i1, o[dt][3] * i1);
    }
}

// ---------------------------------------------------------------------------
extern "C" void kernel_launch(void* const* d_in, const int* in_sizes, int n_in,
                              void* d_out, int out_size)
{
    const float* X    = (const float*)d_in[0];
    const float* mask = (const float*)d_in[1];
    const float* Wq   = (const float*)d_in[2];
    const float* bq   = (const float*)d_in[3];
    const float* Wk   = (const float*)d_in[4];
    const float* bk   = (const float*)d_in[5];
    const float* Wv   = (const float*)d_in[6];
    const float* bv   = (const float*)d_in[7];
    float* out = (float*)d_out;

    static int attr_set = 0;
    if (!attr_set) {
        cudaFuncSetAttribute(qkv_kernel,
                             cudaFuncAttributeMaxDynamicSharedMemorySize, QKV_SMEM);
        cudaFuncSetAttribute(attn_kernel,
                             cudaFuncAttributeMaxDynamicSharedMemorySize, SQ_TOT);
        attr_set = 1;
    }

    f2h_kernel<<<dim3(2048, 4), 256>>>(X, Wq, Wk, Wv);

    dim3 gemm_grid(DM / 128, MTOT / 128, 3);   // (8, 64, 3)
    qkv_kernel<<<gemm_grid, 256, QKV_SMEM>>>(bq, bk, bv);

    dim3 attn_grid(SEQ / 128, NB * NH);        // (16, 64)
    attn_kernel<<<attn_grid, 256, SQ_TOT>>>(mask, out);
}